// round 2
// baseline (speedup 1.0000x reference)
#include <cuda_runtime.h>
#include <cuda_bf16.h>

#define OBS      64
#define ACTD     16
#define DIN      80
#define HID      256
#define TILE_M   64
#define NTHREADS 256
#define DT       0.05f

// Tsit5 tableau
__constant__ float c_A[6][5] = {
    {0.f, 0.f, 0.f, 0.f, 0.f},
    {0.161f, 0.f, 0.f, 0.f, 0.f},
    {-0.008480655492356989f, 0.335480655492357f, 0.f, 0.f, 0.f},
    {2.8971530571054935f, -6.359448489975075f, 4.3622954328695815f, 0.f, 0.f},
    {5.325864828439257f, -11.748883564062828f, 7.4955393428898365f, -0.09249506636175525f, 0.f},
    {5.86145544294642f, -12.92096931784711f, 8.159367898576159f, -0.071584973281401f, -0.028269050394068383f},
};
__constant__ float c_B[6] = {
    0.09646076681806523f, 0.01f, 0.4798896504144996f,
    1.379008574103742f, -3.290069515436081f, 2.324710524099774f
};

// SMEM layout (floats unless noted):
//  sY0   [64*64]      y0 tile
//  sY1   [64*64]      fp32 output accumulator
//  sBufA [64*256]     x_in (cols 0..79) then h2
//  sBufB [64*256]     h1
//  sW    [16*256]     weight K-panel
//  sAct  [64*16]      actions tile
//  sK    [5*64*64]    bf16 stage derivatives
// total = 184320 + 40960 = 225280 bytes
#define SMEM_BYTES 225280

// MODE 0: silu epilogue -> sOut (row stride 256)
// MODE 1: k epilogue    -> bf16 sKdst (optional) + sY1 += y1c * k
template<int K, int N, int MODE>
__device__ __forceinline__ void gemm_tile(
    const float* __restrict__ sA,          // [64][256]
    const float* __restrict__ gW,          // [K][N] row-major, global
    const float* __restrict__ gB,          // [N] bias, global
    float* __restrict__ sW,                // [16*N] panel
    float* __restrict__ sOut,
    __nv_bfloat16* __restrict__ sKdst,
    float* __restrict__ sY1, float y1c,
    int tid)
{
    constexpr int NJ = N / 32;
    const int mt = tid >> 5;   // warp id = M sub-row (broadcast A reads)
    const int nt = tid & 31;   // lane    = N column   (conflict-free B reads)

    float acc[8][NJ];
    {
        float bias[NJ];
        #pragma unroll
        for (int j = 0; j < NJ; j++) bias[j] = gB[nt + 32 * j];
        #pragma unroll
        for (int i = 0; i < 8; i++)
            #pragma unroll
            for (int j = 0; j < NJ; j++) acc[i][j] = bias[j];
    }

    for (int k0 = 0; k0 < K; k0 += 16) {
        __syncthreads();   // protect sW (and, on first iter, A-operand build)
        {   // panel rows are contiguous in global: flat float4 copy
            const float4* src = reinterpret_cast<const float4*>(gW + k0 * N);
            float4* dst = reinterpret_cast<float4*>(sW);
            for (int idx = tid; idx < 16 * N / 4; idx += NTHREADS) dst[idx] = src[idx];
        }
        __syncthreads();
        #pragma unroll
        for (int kk = 0; kk < 16; kk++) {
            float a[8], b[NJ];
            #pragma unroll
            for (int i = 0; i < 8; i++) a[i] = sA[(mt + 8 * i) * 256 + k0 + kk];
            #pragma unroll
            for (int j = 0; j < NJ; j++) b[j] = sW[kk * N + nt + 32 * j];
            #pragma unroll
            for (int i = 0; i < 8; i++)
                #pragma unroll
                for (int j = 0; j < NJ; j++) acc[i][j] = fmaf(a[i], b[j], acc[i][j]);
        }
    }

    #pragma unroll
    for (int i = 0; i < 8; i++) {
        const int m = mt + 8 * i;
        #pragma unroll
        for (int j = 0; j < NJ; j++) {
            const int n = nt + 32 * j;
            float v = acc[i][j];
            if (MODE == 0) {
                sOut[m * 256 + n] = v / (1.0f + __expf(-v));   // silu
            } else {
                if (sKdst) sKdst[m * OBS + n] = __float2bfloat16(v);
                sY1[m * OBS + n] += y1c * v;                   // fp32-precision k into y1
            }
        }
    }
    __syncthreads();   // writers done before next phase touches buffers
}

extern __shared__ float smem[];

__global__ __launch_bounds__(NTHREADS, 1)
void tsit5_mlp_kernel(
    const float* __restrict__ obs, const float* __restrict__ act,
    const float* __restrict__ W1, const float* __restrict__ b1,
    const float* __restrict__ W2, const float* __restrict__ b2,
    const float* __restrict__ W3, const float* __restrict__ b3,
    float* __restrict__ out)
{
    float* sY0   = smem;                       // 4096
    float* sY1   = sY0 + 4096;                 // 4096
    float* sBufA = sY1 + 4096;                 // 16384
    float* sBufB = sBufA + 16384;              // 16384
    float* sW    = sBufB + 16384;              // 4096
    float* sAct  = sW + 4096;                  // 1024
    __nv_bfloat16* sK = reinterpret_cast<__nv_bfloat16*>(sAct + 1024); // 5*4096

    const int tid = threadIdx.x;
    const long base = (long)blockIdx.x * TILE_M;

    {   // load y0 (also seed y1) and actions — coalesced float4
        const float4* gobs = reinterpret_cast<const float4*>(obs + base * OBS);
        for (int idx = tid; idx < TILE_M * OBS / 4; idx += NTHREADS) {
            float4 v = gobs[idx];
            reinterpret_cast<float4*>(sY0)[idx] = v;
            reinterpret_cast<float4*>(sY1)[idx] = v;
        }
        const float4* gact = reinterpret_cast<const float4*>(act + base * ACTD);
        for (int idx = tid; idx < TILE_M * ACTD / 4; idx += NTHREADS)
            reinterpret_cast<float4*>(sAct)[idx] = gact[idx];
    }
    __syncthreads();

    #pragma unroll 1    // keep code resident in I$; gemm bodies instantiated once
    for (int st = 0; st < 6; st++) {
        // build x_i = y0 + dt * sum_j a[st][j] * k_j into sBufA cols 0..63
        for (int idx = tid; idx < TILE_M * OBS; idx += NTHREADS) {
            const int m = idx >> 6, c = idx & 63;
            float v = sY0[idx];
            for (int j = 0; j < st; j++)
                v = fmaf(DT * c_A[st][j], __bfloat162float(sK[j * 4096 + idx]), v);
            sBufA[m * 256 + c] = v;
        }
        // actions into cols 64..79
        for (int idx = tid; idx < TILE_M * ACTD; idx += NTHREADS) {
            const int m = idx >> 4, c = idx & 15;
            sBufA[m * 256 + OBS + c] = sAct[idx];
        }
        // (gemm_tile's leading __syncthreads covers the build->read hazard)
        gemm_tile<DIN, HID, 0>(sBufA, W1, b1, sW, sBufB, nullptr, nullptr, 0.f, tid);
        gemm_tile<HID, HID, 0>(sBufB, W2, b2, sW, sBufA, nullptr, nullptr, 0.f, tid);
        gemm_tile<HID, OBS, 1>(sBufA, W3, b3, sW, nullptr,
                               (st < 5) ? (sK + st * 4096) : nullptr,
                               sY1, DT * c_B[st], tid);
    }

    {   // y1 -> out
        float4* gout = reinterpret_cast<float4*>(out + base * OBS);
        for (int idx = tid; idx < TILE_M * OBS / 4; idx += NTHREADS)
            gout[idx] = reinterpret_cast<const float4*>(sY1)[idx];
    }
}

extern "C" void kernel_launch(void* const* d_in, const int* in_sizes, int n_in,
                              void* d_out, int out_size)
{
    const float* obs = (const float*)d_in[0];
    const float* act = (const float*)d_in[1];
    const float* W1  = (const float*)d_in[2];
    const float* b1  = (const float*)d_in[3];
    const float* W2  = (const float*)d_in[4];
    const float* b2  = (const float*)d_in[5];
    const float* W3  = (const float*)d_in[6];
    const float* b3  = (const float*)d_in[7];
    float* out = (float*)d_out;

    const int batch = in_sizes[0] / OBS;     // 131072
    const int grid = batch / TILE_M;         // 2048

    cudaFuncSetAttribute(tsit5_mlp_kernel,
                         cudaFuncAttributeMaxDynamicSharedMemorySize, SMEM_BYTES);

    tsit5_mlp_kernel<<<grid, NTHREADS, SMEM_BYTES>>>(
        obs, act, W1, b1, W2, b2, W3, b3, out);
}

// round 7
// speedup vs baseline: 2.1816x; 2.1816x over previous
#include <cuda_runtime.h>
#include <cuda_bf16.h>
#include <cstdint>

#define NT    256
#define GRID  148
#define DTf   0.05f
#define MAXTILES 1024

// ---------------- Tsit5 tableau ----------------
__constant__ float c_A[6][5] = {
    {0.f, 0.f, 0.f, 0.f, 0.f},
    {0.161f, 0.f, 0.f, 0.f, 0.f},
    {-0.008480655492356989f, 0.335480655492357f, 0.f, 0.f, 0.f},
    {2.8971530571054935f, -6.359448489975075f, 4.3622954328695815f, 0.f, 0.f},
    {5.325864828439257f, -11.748883564062828f, 7.4955393428898365f, -0.09249506636175525f, 0.f},
    {5.86145544294642f, -12.92096931784711f, 8.159367898576159f, -0.071584973281401f, -0.028269050394068383f},
};
__constant__ float c_Bc[6] = {
    0.09646076681806523f, 0.01f, 0.4798896504144996f,
    1.379008574103742f, -3.290069515436081f, 2.324710524099774f
};

// k_1..k_5 stage derivatives, bf16x2 fragments, [tile][stage][q][tid] (coalesced on tid).
// Each thread reads back only values it wrote -> no cross-thread sync needed.
__device__ uint32_t g_k[(size_t)MAXTILES * 5 * 16 * NT];

// ---------------- SMEM layout (bytes) ----------------
// Weights as bf16 in mma.sync B-fragment order: frag = 32 lanes x 8B -> one LDS.64/lane.
#define OW1 0          // 5 ksteps * 32 nfrags * 256B = 40960
#define OW2 40960      // 16 * 32 * 256B = 131072
#define OW3 172032     // 16 *  8 * 256B = 32768
#define OB1 204800     // 256 f32
#define OB2 205824     // 256 f32
#define OB3 206848     // 64 f32
#define SMEM_BYTES 207360

// ---------------- helpers ----------------
__device__ __forceinline__ uint32_t packbf(float lo, float hi) {
    uint32_t r; asm("cvt.rn.bf16x2.f32 %0, %1, %2;" : "=r"(r) : "f"(hi), "f"(lo)); return r;
}
__device__ __forceinline__ float2 unpackbf(uint32_t v) {
    __nv_bfloat162 b = *reinterpret_cast<__nv_bfloat162*>(&v);
    return make_float2(__bfloat162float(b.x), __bfloat162float(b.y));
}
__device__ __forceinline__ float tanh_fast(float x) {
    float y; asm("tanh.approx.f32 %0, %1;" : "=f"(y) : "f"(x)); return y;
}
__device__ __forceinline__ float silu(float x) {
    float t = tanh_fast(0.5f * x);           // sigmoid(x) = 0.5*(tanh(x/2)+1)
    return fmaf(x, 0.5f * t, 0.5f * x);
}
__device__ __forceinline__ uint32_t ld2bf(const float* p) {
    float2 v = *(const float2*)p; return packbf(v.x, v.y);
}
// m16n8k16 row.col bf16 MMA, fp32 accumulate (legal on base sm_100 target)
__device__ __forceinline__ void mma_bf16(float* c, const uint32_t* a, uint2 b) {
    asm volatile(
        "mma.sync.aligned.m16n8k16.row.col.f32.bf16.bf16.f32 "
        "{%0,%1,%2,%3},{%4,%5,%6,%7},{%8,%9},{%0,%1,%2,%3};"
        : "+f"(c[0]), "+f"(c[1]), "+f"(c[2]), "+f"(c[3])
        : "r"(a[0]), "r"(a[1]), "r"(a[2]), "r"(a[3]), "r"(b.x), "r"(b.y));
}

// Convert W[K][N] (row-major f32) -> bf16 B-fragment layout in SMEM.
__device__ void conv_w(const float* __restrict__ G, int K, int N, char* dst, int tid) {
    const int NF = N >> 3;
    for (int idx = tid; idx < K * N; idx += NT) {
        int k = idx / N, n = idx - k * N;
        int lane = (n & 7) * 4 + ((k & 7) >> 1);
        int off = ((((k >> 4) * NF + (n >> 3)) * 32 + lane) << 3)
                  + (((k >> 3) & 1) << 2) + ((k & 1) << 1);
        *(__nv_bfloat16*)(dst + off) = __float2bfloat16(G[idx]);
    }
}

extern __shared__ char sm[];

__global__ void __launch_bounds__(NT, 1)
tsit5_mma_kernel(const float* __restrict__ obs, const float* __restrict__ act,
                 const float* __restrict__ gW1, const float* __restrict__ gb1,
                 const float* __restrict__ gW2, const float* __restrict__ gb2,
                 const float* __restrict__ gW3, const float* __restrict__ gb3,
                 float* __restrict__ out, int ntiles)
{
    const int tid = threadIdx.x;

    // ---- one-time: weights -> fragment SMEM, biases -> SMEM ----
    conv_w(gW1,  80, 256, sm + OW1, tid);
    conv_w(gW2, 256, 256, sm + OW2, tid);
    conv_w(gW3, 256,  64, sm + OW3, tid);
    for (int i = tid; i < 256; i += NT) {
        ((float*)(sm + OB1))[i] = gb1[i];
        ((float*)(sm + OB2))[i] = gb2[i];
    }
    for (int i = tid; i < 64; i += NT) ((float*)(sm + OB3))[i] = gb3[i];
    __syncthreads();

    const uint2* W1F = (const uint2*)(sm + OW1);
    const uint2* W2F = (const uint2*)(sm + OW2);
    const uint2* W3F = (const uint2*)(sm + OW3);
    const float* B1  = (const float*)(sm + OB1);
    const float* B2  = (const float*)(sm + OB2);
    const float* B3  = (const float*)(sm + OB3);

    const int w  = tid >> 5, l = tid & 31;
    const int m0 = w * 16;              // warp owns rows m0..m0+15 of the 128-row tile
    const int rl = l >> 2;              // fragment row (low half)
    const int cp = (l & 3) * 2;         // fragment column pair base

    for (int tile = blockIdx.x; tile < ntiles; tile += GRID) {
        const long rowlo = (long)tile * 128 + m0 + rl;
        const float* obs_lo = obs + rowlo * 64;
        const float* obs_hi = obs_lo + 8 * 64;
        uint32_t* kt = g_k + ((size_t)tile * 5) * 16 * NT + tid;   // [stage][q][tid]

        // ---- load y0 / action fragments (bf16-packed, mma A layout) ----
        uint32_t y0f[4][4];
        #pragma unroll
        for (int ks = 0; ks < 4; ks++) {
            y0f[ks][0] = ld2bf(obs_lo + ks * 16 + cp);
            y0f[ks][1] = ld2bf(obs_hi + ks * 16 + cp);
            y0f[ks][2] = ld2bf(obs_lo + ks * 16 + 8 + cp);
            y0f[ks][3] = ld2bf(obs_hi + ks * 16 + 8 + cp);
        }
        uint32_t af[4];
        {
            const float* act_lo = act + rowlo * 16;
            af[0] = ld2bf(act_lo + cp);        af[1] = ld2bf(act_lo + 128 + cp);
            af[2] = ld2bf(act_lo + 8 + cp);    af[3] = ld2bf(act_lo + 128 + 8 + cp);
        }

        #pragma unroll
        for (int st = 0; st < 6; st++) {
            // ---- build x_st fragments: y0 + dt * sum_j a[st][j] * k_j (k from L2 scratch) ----
            uint32_t xf[4][4];
            #pragma unroll
            for (int ks = 0; ks < 4; ks++)
                #pragma unroll
                for (int r = 0; r < 4; r++) {
                    const int q = ks * 4 + r;
                    float2 v = unpackbf(y0f[ks][r]);
                    #pragma unroll
                    for (int j = 0; j < 5; j++)
                        if (j < st) {
                            float a = DTf * c_A[st][j];
                            float2 kk = unpackbf(kt[(j * 16 + q) * NT]);
                            v.x = fmaf(a, kk.x, v.x);
                            v.y = fmaf(a, kk.y, v.y);
                        }
                    xf[ks][r] = packbf(v.x, v.y);
                }

            // ---- GEMM1: h1[128,256] = silu(X[128,80] @ W1 + b1) -> hA frags ----
            uint32_t hA[16][4];
            #pragma unroll
            for (int c = 0; c < 4; c++) {
                float acc[8][4];
                #pragma unroll
                for (int nf = 0; nf < 8; nf++) {
                    float2 bb = *(const float2*)(B1 + c * 64 + nf * 8 + cp);
                    acc[nf][0] = bb.x; acc[nf][1] = bb.y;
                    acc[nf][2] = bb.x; acc[nf][3] = bb.y;
                }
                #pragma unroll
                for (int ks = 0; ks < 4; ks++)
                    #pragma unroll
                    for (int nf = 0; nf < 8; nf++)
                        mma_bf16(acc[nf], xf[ks], W1F[(ks * 32 + c * 8 + nf) * 32 + l]);
                #pragma unroll
                for (int nf = 0; nf < 8; nf++)
                    mma_bf16(acc[nf], af, W1F[(4 * 32 + c * 8 + nf) * 32 + l]);
                #pragma unroll
                for (int nf = 0; nf < 8; nf++) {
                    hA[c * 4 + (nf >> 1)][(nf & 1) * 2 + 0] =
                        packbf(silu(acc[nf][0]), silu(acc[nf][1]));
                    hA[c * 4 + (nf >> 1)][(nf & 1) * 2 + 1] =
                        packbf(silu(acc[nf][2]), silu(acc[nf][3]));
                }
            }

            // ---- GEMM2 (silu) with fused GEMM3 partials ----
            float acc3[8][4];
            #pragma unroll
            for (int nf = 0; nf < 8; nf++)
                acc3[nf][0] = acc3[nf][1] = acc3[nf][2] = acc3[nf][3] = 0.f;

            #pragma unroll
            for (int c = 0; c < 4; c++) {
                float acc[8][4];
                #pragma unroll
                for (int nf = 0; nf < 8; nf++) {
                    float2 bb = *(const float2*)(B2 + c * 64 + nf * 8 + cp);
                    acc[nf][0] = bb.x; acc[nf][1] = bb.y;
                    acc[nf][2] = bb.x; acc[nf][3] = bb.y;
                }
                #pragma unroll
                for (int ks = 0; ks < 16; ks++)
                    #pragma unroll
                    for (int nf = 0; nf < 8; nf++)
                        mma_bf16(acc[nf], hA[ks], W2F[(ks * 32 + c * 8 + nf) * 32 + l]);
                // h2 chunk (4 ksteps) -> transient frags, feed GEMM3 immediately
                uint32_t ht[4][4];
                #pragma unroll
                for (int nf = 0; nf < 8; nf++) {
                    ht[nf >> 1][(nf & 1) * 2 + 0] =
                        packbf(silu(acc[nf][0]), silu(acc[nf][1]));
                    ht[nf >> 1][(nf & 1) * 2 + 1] =
                        packbf(silu(acc[nf][2]), silu(acc[nf][3]));
                }
                #pragma unroll
                for (int j = 0; j < 4; j++)
                    #pragma unroll
                    for (int nf = 0; nf < 8; nf++)
                        mma_bf16(acc3[nf], ht[j], W3F[((c * 4 + j) * 8 + nf) * 32 + l]);
            }

            // ---- GEMM3 epilogue: k_st = acc3 + b3 -> scratch (or final y1) ----
            if (st < 5) {
                #pragma unroll
                for (int nf = 0; nf < 8; nf++) {
                    float2 bb = *(const float2*)(B3 + nf * 8 + cp);
                    int q = (nf >> 1) * 4 + (nf & 1) * 2;
                    kt[(st * 16 + q + 0) * NT] = packbf(acc3[nf][0] + bb.x, acc3[nf][1] + bb.y);
                    kt[(st * 16 + q + 1) * NT] = packbf(acc3[nf][2] + bb.x, acc3[nf][3] + bb.y);
                }
            } else {
                // final: y1 = y0(fp32 reload) + dt * sum_j b_j k_j
                float* o_lo = out + rowlo * 64;
                float* o_hi = o_lo + 8 * 64;
                const float d5 = DTf * c_Bc[5];
                #pragma unroll
                for (int nf = 0; nf < 8; nf++) {
                    float2 bb  = *(const float2*)(B3 + nf * 8 + cp);
                    float2 ylo = *(const float2*)(obs_lo + nf * 8 + cp);
                    float2 yhi = *(const float2*)(obs_hi + nf * 8 + cp);
                    float lo0 = fmaf(d5, acc3[nf][0] + bb.x, ylo.x);
                    float lo1 = fmaf(d5, acc3[nf][1] + bb.y, ylo.y);
                    float hi0 = fmaf(d5, acc3[nf][2] + bb.x, yhi.x);
                    float hi1 = fmaf(d5, acc3[nf][3] + bb.y, yhi.y);
                    int ql = (nf >> 1) * 4 + (nf & 1) * 2, qh = ql + 1;
                    #pragma unroll
                    for (int j = 0; j < 5; j++) {
                        float d = DTf * c_Bc[j];
                        float2 klo = unpackbf(kt[(j * 16 + ql) * NT]);
                        float2 khi = unpackbf(kt[(j * 16 + qh) * NT]);
                        lo0 = fmaf(d, klo.x, lo0); lo1 = fmaf(d, klo.y, lo1);
                        hi0 = fmaf(d, khi.x, hi0); hi1 = fmaf(d, khi.y, hi1);
                    }
                    *(float2*)(o_lo + nf * 8 + cp) = make_float2(lo0, lo1);
                    *(float2*)(o_hi + nf * 8 + cp) = make_float2(hi0, hi1);
                }
            }
        }
    }
}

extern "C" void kernel_launch(void* const* d_in, const int* in_sizes, int n_in,
                              void* d_out, int out_size)
{
    const float* obs = (const float*)d_in[0];
    const float* act = (const float*)d_in[1];
    const float* W1  = (const float*)d_in[2];
    const float* b1  = (const float*)d_in[3];
    const float* W2  = (const float*)d_in[4];
    const float* b2  = (const float*)d_in[5];
    const float* W3  = (const float*)d_in[6];
    const float* b3  = (const float*)d_in[7];
    float* out = (float*)d_out;

    const int batch  = in_sizes[0] / 64;
    int ntiles = batch / 128;
    if (ntiles > MAXTILES) ntiles = MAXTILES;   // scratch bound (batch is fixed 131072 -> 1024)

    cudaFuncSetAttribute(tsit5_mma_kernel,
                         cudaFuncAttributeMaxDynamicSharedMemorySize, SMEM_BYTES);

    tsit5_mma_kernel<<<GRID, NT, SMEM_BYTES>>>(obs, act, W1, b1, W2, b2, W3, b3, out, ntiles);
}

// round 8
// speedup vs baseline: 10.9123x; 5.0021x over previous
#include <cuda_runtime.h>
#include <cuda_bf16.h>
#include <cstdint>

#define NT    256
#define GRID  148
#define DTf   0.05f
#define MAXTILES 1024

// ---------------- Tsit5 tableau ----------------
__constant__ float c_A[6][5] = {
    {0.f, 0.f, 0.f, 0.f, 0.f},
    {0.161f, 0.f, 0.f, 0.f, 0.f},
    {-0.008480655492356989f, 0.335480655492357f, 0.f, 0.f, 0.f},
    {2.8971530571054935f, -6.359448489975075f, 4.3622954328695815f, 0.f, 0.f},
    {5.325864828439257f, -11.748883564062828f, 7.4955393428898365f, -0.09249506636175525f, 0.f},
    {5.86145544294642f, -12.92096931784711f, 8.159367898576159f, -0.071584973281401f, -0.028269050394068383f},
};
__constant__ float c_Bc[6] = {
    0.09646076681806523f, 0.01f, 0.4798896504144996f,
    1.379008574103742f, -3.290069515436081f, 2.324710524099774f
};

// k_1..k_5 stage derivatives, bf16x2 fragments, [tile][stage][q][tid] (coalesced on tid).
// Each thread reads back only values it wrote -> no cross-thread sync needed.
__device__ uint32_t g_k[(size_t)MAXTILES * 5 * 16 * NT];

// ---------------- SMEM layout (bytes) ----------------
// Weights as bf16 in mma.sync B-fragment order: frag = 32 lanes x 8B -> one LDS.64/lane.
#define OW1 0          // 5 ksteps * 32 nfrags * 256B = 40960
#define OW2 40960      // 16 * 32 * 256B = 131072
#define OW3 172032     // 16 *  8 * 256B = 32768
#define OB1 204800     // 256 f32
#define OB2 205824     // 256 f32
#define OB3 206848     // 64 f32
#define SMEM_BYTES 207360

// ---------------- helpers ----------------
__device__ __forceinline__ uint32_t packbf(float lo, float hi) {
    uint32_t r; asm("cvt.rn.bf16x2.f32 %0, %1, %2;" : "=r"(r) : "f"(hi), "f"(lo)); return r;
}
__device__ __forceinline__ float2 unpackbf(uint32_t v) {
    __nv_bfloat162 b = *reinterpret_cast<__nv_bfloat162*>(&v);
    return make_float2(__bfloat162float(b.x), __bfloat162float(b.y));
}
__device__ __forceinline__ float tanh_fast(float x) {
    float y; asm("tanh.approx.f32 %0, %1;" : "=f"(y) : "f"(x)); return y;
}
__device__ __forceinline__ float silu(float x) {
    float t = tanh_fast(0.5f * x);           // sigmoid(x) = 0.5*(tanh(x/2)+1)
    return fmaf(x, 0.5f * t, 0.5f * x);
}
// m16n8k16 row.col bf16 MMA, fp32 accumulate (legal on base sm_100 target)
__device__ __forceinline__ void mma_bf16(float* c, const uint32_t* a, uint2 b) {
    asm volatile(
        "mma.sync.aligned.m16n8k16.row.col.f32.bf16.bf16.f32 "
        "{%0,%1,%2,%3},{%4,%5,%6,%7},{%8,%9},{%0,%1,%2,%3};"
        : "+f"(c[0]), "+f"(c[1]), "+f"(c[2]), "+f"(c[3])
        : "r"(a[0]), "r"(a[1]), "r"(a[2]), "r"(a[3]), "r"(b.x), "r"(b.y));
}

// Convert W[K][N] (row-major f32) -> bf16 B-fragment layout in SMEM.
__device__ void conv_w(const float* __restrict__ G, int K, int N, char* dst, int tid) {
    const int NF = N >> 3;
    for (int idx = tid; idx < K * N; idx += NT) {
        int k = idx / N, n = idx - k * N;
        int lane = (n & 7) * 4 + ((k & 7) >> 1);
        int off = ((((k >> 4) * NF + (n >> 3)) * 32 + lane) << 3)
                  + (((k >> 3) & 1) << 2) + ((k & 1) << 1);
        *(__nv_bfloat16*)(dst + off) = __float2bfloat16(G[idx]);
    }
}

extern __shared__ char sm[];

__global__ void __launch_bounds__(NT, 1)
tsit5_mma_kernel(const float* __restrict__ obs, const float* __restrict__ act,
                 const float* __restrict__ gW1, const float* __restrict__ gb1,
                 const float* __restrict__ gW2, const float* __restrict__ gb2,
                 const float* __restrict__ gW3, const float* __restrict__ gb3,
                 float* __restrict__ out, int ntiles)
{
    const int tid = threadIdx.x;

    // ---- one-time: weights -> fragment SMEM, biases -> SMEM ----
    conv_w(gW1,  80, 256, sm + OW1, tid);
    conv_w(gW2, 256, 256, sm + OW2, tid);
    conv_w(gW3, 256,  64, sm + OW3, tid);
    for (int i = tid; i < 256; i += NT) {
        ((float*)(sm + OB1))[i] = gb1[i];
        ((float*)(sm + OB2))[i] = gb2[i];
    }
    for (int i = tid; i < 64; i += NT) ((float*)(sm + OB3))[i] = gb3[i];
    __syncthreads();

    const uint2* W1F = (const uint2*)(sm + OW1);
    const uint2* W2F = (const uint2*)(sm + OW2);
    const uint2* W3F = (const uint2*)(sm + OW3);
    const float* B1  = (const float*)(sm + OB1);
    const float* B2  = (const float*)(sm + OB2);
    const float* B3  = (const float*)(sm + OB3);

    const int w  = tid >> 5, l = tid & 31;
    const int m0 = w * 16;              // warp owns rows m0..m0+15 of the 128-row tile
    const int rl = l >> 2;              // fragment row (low half)
    const int cp = (l & 3) * 2;         // fragment column pair base

    for (int tile = blockIdx.x; tile < ntiles; tile += GRID) {
        const long rowlo = (long)tile * 128 + m0 + rl;
        const float* obs_lo = obs + rowlo * 64;
        const float* obs_hi = obs_lo + 8 * 64;
        uint32_t* kt = g_k + ((size_t)tile * 5) * 16 * NT + tid;   // [stage][q][tid]

        // action fragments (bf16-packed, mma A layout) — small, keep in regs
        uint32_t af[4];
        {
            const float* act_lo = act + rowlo * 16;
            float2 v;
            v = *(const float2*)(act_lo + cp);           af[0] = packbf(v.x, v.y);
            v = *(const float2*)(act_lo + 128 + cp);     af[1] = packbf(v.x, v.y);
            v = *(const float2*)(act_lo + 8 + cp);       af[2] = packbf(v.x, v.y);
            v = *(const float2*)(act_lo + 128 + 8 + cp); af[3] = packbf(v.x, v.y);
        }

        #pragma unroll 1   // ONE body copy: keeps regs < 255 (no spills), small I$
        for (int st = 0; st < 6; st++) {
            // ---- build x_st fragments: fp32 y0 (gmem, L2-hot) + dt * sum_j a[st][j]*k_j ----
            uint32_t xf[4][4];
            #pragma unroll
            for (int ks = 0; ks < 4; ks++)
                #pragma unroll
                for (int r = 0; r < 4; r++) {
                    const int q = ks * 4 + r;
                    const float* yp = ((r & 1) ? obs_hi : obs_lo) + ks * 16 + (r >> 1) * 8 + cp;
                    float2 v = *(const float2*)yp;
                    #pragma unroll
                    for (int j = 0; j < 5; j++)
                        if (j < st) {
                            float a = DTf * c_A[st][j];
                            float2 kk = unpackbf(kt[(j * 16 + q) * NT]);
                            v.x = fmaf(a, kk.x, v.x);
                            v.y = fmaf(a, kk.y, v.y);
                        }
                    xf[ks][r] = packbf(v.x, v.y);
                }

            // ---- GEMM1: h1[128,256] = silu(X[128,80] @ W1 + b1) -> hA frags ----
            uint32_t hA[16][4];
            #pragma unroll
            for (int c = 0; c < 4; c++) {
                float acc[8][4];
                #pragma unroll
                for (int nf = 0; nf < 8; nf++) {
                    float2 bb = *(const float2*)(B1 + c * 64 + nf * 8 + cp);
                    acc[nf][0] = bb.x; acc[nf][1] = bb.y;
                    acc[nf][2] = bb.x; acc[nf][3] = bb.y;
                }
                #pragma unroll
                for (int ks = 0; ks < 4; ks++)
                    #pragma unroll
                    for (int nf = 0; nf < 8; nf++)
                        mma_bf16(acc[nf], xf[ks], W1F[(ks * 32 + c * 8 + nf) * 32 + l]);
                #pragma unroll
                for (int nf = 0; nf < 8; nf++)
                    mma_bf16(acc[nf], af, W1F[(4 * 32 + c * 8 + nf) * 32 + l]);
                #pragma unroll
                for (int nf = 0; nf < 8; nf++) {
                    hA[c * 4 + (nf >> 1)][(nf & 1) * 2 + 0] =
                        packbf(silu(acc[nf][0]), silu(acc[nf][1]));
                    hA[c * 4 + (nf >> 1)][(nf & 1) * 2 + 1] =
                        packbf(silu(acc[nf][2]), silu(acc[nf][3]));
                }
            }

            // ---- GEMM2 (silu) with fused GEMM3 partials ----
            float acc3[8][4];
            #pragma unroll
            for (int nf = 0; nf < 8; nf++)
                acc3[nf][0] = acc3[nf][1] = acc3[nf][2] = acc3[nf][3] = 0.f;

            #pragma unroll
            for (int c = 0; c < 4; c++) {
                float acc[8][4];
                #pragma unroll
                for (int nf = 0; nf < 8; nf++) {
                    float2 bb = *(const float2*)(B2 + c * 64 + nf * 8 + cp);
                    acc[nf][0] = bb.x; acc[nf][1] = bb.y;
                    acc[nf][2] = bb.x; acc[nf][3] = bb.y;
                }
                #pragma unroll
                for (int ks = 0; ks < 16; ks++)
                    #pragma unroll
                    for (int nf = 0; nf < 8; nf++)
                        mma_bf16(acc[nf], hA[ks], W2F[(ks * 32 + c * 8 + nf) * 32 + l]);
                // h2 chunk (4 ksteps) -> transient frags, feed GEMM3 immediately
                uint32_t ht[4][4];
                #pragma unroll
                for (int nf = 0; nf < 8; nf++) {
                    ht[nf >> 1][(nf & 1) * 2 + 0] =
                        packbf(silu(acc[nf][0]), silu(acc[nf][1]));
                    ht[nf >> 1][(nf & 1) * 2 + 1] =
                        packbf(silu(acc[nf][2]), silu(acc[nf][3]));
                }
                #pragma unroll
                for (int j = 0; j < 4; j++)
                    #pragma unroll
                    for (int nf = 0; nf < 8; nf++)
                        mma_bf16(acc3[nf], ht[j], W3F[((c * 4 + j) * 8 + nf) * 32 + l]);
            }

            // ---- GEMM3 epilogue: k_st = acc3 + b3 -> scratch (or final y1) ----
            if (st < 5) {
                #pragma unroll
                for (int nf = 0; nf < 8; nf++) {
                    float2 bb = *(const float2*)(B3 + nf * 8 + cp);
                    int q = (nf >> 1) * 4 + (nf & 1) * 2;
                    kt[(st * 16 + q + 0) * NT] = packbf(acc3[nf][0] + bb.x, acc3[nf][1] + bb.y);
                    kt[(st * 16 + q + 1) * NT] = packbf(acc3[nf][2] + bb.x, acc3[nf][3] + bb.y);
                }
            } else {
                // final: y1 = y0(fp32) + dt * sum_j b_j k_j
                float* o_lo = out + rowlo * 64;
                float* o_hi = o_lo + 8 * 64;
                const float d5 = DTf * c_Bc[5];
                #pragma unroll
                for (int nf = 0; nf < 8; nf++) {
                    float2 bb  = *(const float2*)(B3 + nf * 8 + cp);
                    float2 ylo = *(const float2*)(obs_lo + nf * 8 + cp);
                    float2 yhi = *(const float2*)(obs_hi + nf * 8 + cp);
                    float lo0 = fmaf(d5, acc3[nf][0] + bb.x, ylo.x);
                    float lo1 = fmaf(d5, acc3[nf][1] + bb.y, ylo.y);
                    float hi0 = fmaf(d5, acc3[nf][2] + bb.x, yhi.x);
                    float hi1 = fmaf(d5, acc3[nf][3] + bb.y, yhi.y);
                    int ql = (nf >> 1) * 4 + (nf & 1) * 2, qh = ql + 1;
                    #pragma unroll
                    for (int j = 0; j < 5; j++) {
                        float d = DTf * c_Bc[j];
                        float2 klo = unpackbf(kt[(j * 16 + ql) * NT]);
                        float2 khi = unpackbf(kt[(j * 16 + qh) * NT]);
                        lo0 = fmaf(d, klo.x, lo0); lo1 = fmaf(d, klo.y, lo1);
                        hi0 = fmaf(d, khi.x, hi0); hi1 = fmaf(d, khi.y, hi1);
                    }
                    *(float2*)(o_lo + nf * 8 + cp) = make_float2(lo0, lo1);
                    *(float2*)(o_hi + nf * 8 + cp) = make_float2(hi0, hi1);
                }
            }
        }
    }
}

extern "C" void kernel_launch(void* const* d_in, const int* in_sizes, int n_in,
                              void* d_out, int out_size)
{
    const float* obs = (const float*)d_in[0];
    const float* act = (const float*)d_in[1];
    const float* W1  = (const float*)d_in[2];
    const float* b1  = (const float*)d_in[3];
    const float* W2  = (const float*)d_in[4];
    const float* b2  = (const float*)d_in[5];
    const float* W3  = (const float*)d_in[6];
    const float* b3  = (const float*)d_in[7];
    float* out = (float*)d_out;

    const int batch  = in_sizes[0] / 64;
    int ntiles = batch / 128;
    if (ntiles > MAXTILES) ntiles = MAXTILES;   // scratch bound (batch fixed 131072 -> 1024)

    cudaFuncSetAttribute(tsit5_mma_kernel,
                         cudaFuncAttributeMaxDynamicSharedMemorySize, SMEM_BYTES);

    tsit5_mma_kernel<<<GRID, NT, SMEM_BYTES>>>(obs, act, W1, b1, W2, b2, W3, b3, out, ntiles);
}

// round 9
// speedup vs baseline: 11.6574x; 1.0683x over previous
#include <cuda_runtime.h>
#include <cuda_bf16.h>
#include <cstdint>

#define NT    256
#define GRID  148
#define DTf   0.05f
#define MAXTILES 1024

// ---------------- Tsit5 tableau ----------------
__constant__ float c_A[6][5] = {
    {0.f, 0.f, 0.f, 0.f, 0.f},
    {0.161f, 0.f, 0.f, 0.f, 0.f},
    {-0.008480655492356989f, 0.335480655492357f, 0.f, 0.f, 0.f},
    {2.8971530571054935f, -6.359448489975075f, 4.3622954328695815f, 0.f, 0.f},
    {5.325864828439257f, -11.748883564062828f, 7.4955393428898365f, -0.09249506636175525f, 0.f},
    {5.86145544294642f, -12.92096931784711f, 8.159367898576159f, -0.071584973281401f, -0.028269050394068383f},
};
__constant__ float c_Bc[6] = {
    0.09646076681806523f, 0.01f, 0.4798896504144996f,
    1.379008574103742f, -3.290069515436081f, 2.324710524099774f
};

// k_1..k_5 stage derivatives, bf16x2 fragments, [tile][stage][q][tid] (coalesced on tid).
__device__ uint32_t g_k[(size_t)MAXTILES * 5 * 16 * NT];

// ---------------- SMEM layout (bytes) ----------------
// Weights as bf16 in mma.sync B-fragment order, fragments LINEARIZED in each
// GEMM's traversal order so inner loops walk a single pointer (+256B stride).
#define OW1 0          // 4 c * 5 ks * 8 nf = 160 frags * 256B = 40960
#define OW2 40960      // 4 c * 16 ks * 8 nf = 512 frags       = 131072
#define OW3 172032     // 16 ks * 8 nf = 128 frags             = 32768
#define OB1 204800     // 256 f32
#define OB2 205824     // 256 f32
#define OB3 206848     // 64 f32
#define SMEM_BYTES 207360

// ---------------- helpers ----------------
__device__ __forceinline__ uint32_t packbf(float lo, float hi) {
    uint32_t r; asm("cvt.rn.bf16x2.f32 %0, %1, %2;" : "=r"(r) : "f"(hi), "f"(lo)); return r;
}
__device__ __forceinline__ float2 unpackbf(uint32_t v) {
    __nv_bfloat162 b = *reinterpret_cast<__nv_bfloat162*>(&v);
    return make_float2(__bfloat162float(b.x), __bfloat162float(b.y));
}
__device__ __forceinline__ float tanh_fast(float x) {
    float y; asm("tanh.approx.f32 %0, %1;" : "=f"(y) : "f"(x)); return y;
}
__device__ __forceinline__ float silu(float x) {
    float t = tanh_fast(0.5f * x);
    return fmaf(x, 0.5f * t, 0.5f * x);
}
__device__ __forceinline__ void mma_bf16(float* c, const uint32_t* a, uint2 b) {
    asm volatile(
        "mma.sync.aligned.m16n8k16.row.col.f32.bf16.bf16.f32 "
        "{%0,%1,%2,%3},{%4,%5,%6,%7},{%8,%9},{%0,%1,%2,%3};"
        : "+f"(c[0]), "+f"(c[1]), "+f"(c[2]), "+f"(c[3])
        : "r"(a[0]), "r"(a[1]), "r"(a[2]), "r"(a[3]), "r"(b.x), "r"(b.y));
}

// W[K][N] row-major f32 -> bf16 B-fragment SMEM, fragment index linearized:
//   MODE 1 (W1): f = c*40  + ks*8 + nf   (c = n>>6, ks = k>>4, nf = (n>>3)&7)
//   MODE 2 (W2): f = c*128 + ks*8 + nf
//   MODE 3 (W3): f = ks*8 + nfg          (N=64: nfg = n>>3)
template<int MODE>
__device__ void conv_w(const float* __restrict__ G, int K, int N, char* dst, int tid) {
    for (int idx = tid; idx < K * N; idx += NT) {
        int k = idx / N, n = idx - k * N;
        int lane = (n & 7) * 4 + ((k & 7) >> 1);
        int ks = k >> 4, nfg = n >> 3;
        int f;
        if (MODE == 1)      f = (nfg >> 3) * 40  + ks * 8 + (nfg & 7);
        else if (MODE == 2) f = (nfg >> 3) * 128 + ks * 8 + (nfg & 7);
        else                f = ks * 8 + nfg;
        int off = ((f * 32 + lane) << 3) + (((k >> 3) & 1) << 2) + ((k & 1) << 1);
        *(__nv_bfloat16*)(dst + off) = __float2bfloat16(G[idx]);
    }
}

extern __shared__ char sm[];

__global__ void __launch_bounds__(NT, 1)
tsit5_mma_kernel(const float* __restrict__ obs, const float* __restrict__ act,
                 const float* __restrict__ gW1, const float* __restrict__ gb1,
                 const float* __restrict__ gW2, const float* __restrict__ gb2,
                 const float* __restrict__ gW3, const float* __restrict__ gb3,
                 float* __restrict__ out, int ntiles)
{
    const int tid = threadIdx.x;

    conv_w<1>(gW1,  80, 256, sm + OW1, tid);
    conv_w<2>(gW2, 256, 256, sm + OW2, tid);
    conv_w<3>(gW3, 256,  64, sm + OW3, tid);
    for (int i = tid; i < 256; i += NT) {
        ((float*)(sm + OB1))[i] = gb1[i];
        ((float*)(sm + OB2))[i] = gb2[i];
    }
    for (int i = tid; i < 64; i += NT) ((float*)(sm + OB3))[i] = gb3[i];
    __syncthreads();

    const uint2* W1F = (const uint2*)(sm + OW1);
    const uint2* W2F = (const uint2*)(sm + OW2);
    const uint2* W3F = (const uint2*)(sm + OW3);
    const float* B1  = (const float*)(sm + OB1);
    const float* B2  = (const float*)(sm + OB2);
    const float* B3  = (const float*)(sm + OB3);

    const int w  = tid >> 5, l = tid & 31;
    const int m0 = w * 16;
    const int rl = l >> 2;
    const int cp = (l & 3) * 2;

    for (int tile = blockIdx.x; tile < ntiles; tile += GRID) {
        const long rowlo = (long)tile * 128 + m0 + rl;
        const float* obs_lo = obs + rowlo * 64;
        const float* obs_hi = obs_lo + 8 * 64;
        uint32_t* kt = g_k + ((size_t)tile * 5) * 16 * NT + tid;

        // action frags live in xa[4] (uniform A-frag array: ks 0..3 = obs/x, ks 4 = act)
        uint32_t xa[5][4];
        {
            const float* act_lo = act + rowlo * 16;
            float2 v;
            v = *(const float2*)(act_lo + cp);           xa[4][0] = packbf(v.x, v.y);
            v = *(const float2*)(act_lo + 128 + cp);     xa[4][1] = packbf(v.x, v.y);
            v = *(const float2*)(act_lo + 8 + cp);       xa[4][2] = packbf(v.x, v.y);
            v = *(const float2*)(act_lo + 128 + 8 + cp); xa[4][3] = packbf(v.x, v.y);
        }

        #pragma unroll 1   // one body copy: no spills, small I$
        for (int st = 0; st < 6; st++) {
            // ---- build x_st A-frags: fp32 y0 (L2-hot) + dt * sum_j a[st][j]*k_j ----
            #pragma unroll
            for (int ks = 0; ks < 4; ks++)
                #pragma unroll
                for (int r = 0; r < 4; r++) {
                    const int q = ks * 4 + r;
                    const float* yp = ((r & 1) ? obs_hi : obs_lo) + ks * 16 + (r >> 1) * 8 + cp;
                    float2 v = *(const float2*)yp;
                    #pragma unroll
                    for (int j = 0; j < 5; j++)
                        if (j < st) {
                            float a = DTf * c_A[st][j];
                            float2 kk = unpackbf(kt[(j * 16 + q) * NT]);
                            v.x = fmaf(a, kk.x, v.x);
                            v.y = fmaf(a, kk.y, v.y);
                        }
                    xa[ks][r] = packbf(v.x, v.y);
                }

            // ---- GEMM1: h1 = silu(X @ W1 + b1) -> hA frags (c-loop unrolled: hA const idx) ----
            uint32_t hA[16][4];
            #pragma unroll
            for (int c = 0; c < 4; c++) {
                const uint2* p1 = W1F + (c * 40) * 32 + l;      // linear frag walk
                float acc[8][4];
                #pragma unroll
                for (int nf = 0; nf < 8; nf++) {
                    float2 bb = *(const float2*)(B1 + c * 64 + nf * 8 + cp);
                    acc[nf][0] = bb.x; acc[nf][1] = bb.y;
                    acc[nf][2] = bb.x; acc[nf][3] = bb.y;
                }
                #pragma unroll
                for (int ks = 0; ks < 5; ks++)
                    #pragma unroll
                    for (int nf = 0; nf < 8; nf++)
                        mma_bf16(acc[nf], xa[ks], p1[(ks * 8 + nf) * 32]);
                #pragma unroll
                for (int nf = 0; nf < 8; nf++) {
                    hA[c * 4 + (nf >> 1)][(nf & 1) * 2 + 0] =
                        packbf(silu(acc[nf][0]), silu(acc[nf][1]));
                    hA[c * 4 + (nf >> 1)][(nf & 1) * 2 + 1] =
                        packbf(silu(acc[nf][2]), silu(acc[nf][3]));
                }
            }

            // ---- GEMM2 (silu) + fused GEMM3 partials (c-loop ROLLED: regs/I$) ----
            float acc3[8][4];
            #pragma unroll
            for (int nf = 0; nf < 8; nf++)
                acc3[nf][0] = acc3[nf][1] = acc3[nf][2] = acc3[nf][3] = 0.f;

            #pragma unroll 1
            for (int c = 0; c < 4; c++) {
                const uint2* p2 = W2F + (c * 128) * 32 + l;     // linear frag walk
                const uint2* p3 = W3F + (c * 32) * 32 + l;      // linear frag walk
                float acc[8][4];
                #pragma unroll
                for (int nf = 0; nf < 8; nf++) {
                    float2 bb = *(const float2*)(B2 + c * 64 + nf * 8 + cp);
                    acc[nf][0] = bb.x; acc[nf][1] = bb.y;
                    acc[nf][2] = bb.x; acc[nf][3] = bb.y;
                }
                #pragma unroll
                for (int ks = 0; ks < 16; ks++)
                    #pragma unroll
                    for (int nf = 0; nf < 8; nf++)
                        mma_bf16(acc[nf], hA[ks], p2[(ks * 8 + nf) * 32]);
                uint32_t ht[4][4];
                #pragma unroll
                for (int nf = 0; nf < 8; nf++) {
                    ht[nf >> 1][(nf & 1) * 2 + 0] =
                        packbf(silu(acc[nf][0]), silu(acc[nf][1]));
                    ht[nf >> 1][(nf & 1) * 2 + 1] =
                        packbf(silu(acc[nf][2]), silu(acc[nf][3]));
                }
                #pragma unroll
                for (int j = 0; j < 4; j++)
                    #pragma unroll
                    for (int nf = 0; nf < 8; nf++)
                        mma_bf16(acc3[nf], ht[j], p3[(j * 8 + nf) * 32]);
            }

            // ---- GEMM3 epilogue ----
            if (st < 5) {
                #pragma unroll
                for (int nf = 0; nf < 8; nf++) {
                    float2 bb = *(const float2*)(B3 + nf * 8 + cp);
                    int q = (nf >> 1) * 4 + (nf & 1) * 2;
                    kt[(st * 16 + q + 0) * NT] = packbf(acc3[nf][0] + bb.x, acc3[nf][1] + bb.y);
                    kt[(st * 16 + q + 1) * NT] = packbf(acc3[nf][2] + bb.x, acc3[nf][3] + bb.y);
                }
            } else {
                float* o_lo = out + rowlo * 64;
                float* o_hi = o_lo + 8 * 64;
                const float d5 = DTf * c_Bc[5];
                #pragma unroll
                for (int nf = 0; nf < 8; nf++) {
                    float2 bb  = *(const float2*)(B3 + nf * 8 + cp);
                    float2 ylo = *(const float2*)(obs_lo + nf * 8 + cp);
                    float2 yhi = *(const float2*)(obs_hi + nf * 8 + cp);
                    float lo0 = fmaf(d5, acc3[nf][0] + bb.x, ylo.x);
                    float lo1 = fmaf(d5, acc3[nf][1] + bb.y, ylo.y);
                    float hi0 = fmaf(d5, acc3[nf][2] + bb.x, yhi.x);
                    float hi1 = fmaf(d5, acc3[nf][3] + bb.y, yhi.y);
                    int ql = (nf >> 1) * 4 + (nf & 1) * 2, qh = ql + 1;
                    #pragma unroll
                    for (int j = 0; j < 5; j++) {
                        float d = DTf * c_Bc[j];
                        float2 klo = unpackbf(kt[(j * 16 + ql) * NT]);
                        float2 khi = unpackbf(kt[(j * 16 + qh) * NT]);
                        lo0 = fmaf(d, klo.x, lo0); lo1 = fmaf(d, klo.y, lo1);
                        hi0 = fmaf(d, khi.x, hi0); hi1 = fmaf(d, khi.y, hi1);
                    }
                    *(float2*)(o_lo + nf * 8 + cp) = make_float2(lo0, lo1);
                    *(float2*)(o_hi + nf * 8 + cp) = make_float2(hi0, hi1);
                }
            }
        }
    }
}

extern "C" void kernel_launch(void* const* d_in, const int* in_sizes, int n_in,
                              void* d_out, int out_size)
{
    const float* obs = (const float*)d_in[0];
    const float* act = (const float*)d_in[1];
    const float* W1  = (const float*)d_in[2];
    const float* b1  = (const float*)d_in[3];
    const float* W2  = (const float*)d_in[4];
    const float* b2  = (const float*)d_in[5];
    const float* W3  = (const float*)d_in[6];
    const float* b3  = (const float*)d_in[7];
    float* out = (float*)d_out;

    const int batch  = in_sizes[0] / 64;
    int ntiles = batch / 128;
    if (ntiles > MAXTILES) ntiles = MAXTILES;

    cudaFuncSetAttribute(tsit5_mma_kernel,
                         cudaFuncAttributeMaxDynamicSharedMemorySize, SMEM_BYTES);

    tsit5_mma_kernel<<<GRID, NT, SMEM_BYTES>>>(obs, act, W1, b1, W2, b2, W3, b3, out, ntiles);
}

// round 10
// speedup vs baseline: 11.8370x; 1.0154x over previous
#include <cuda_runtime.h>
#include <cuda_bf16.h>
#include <cstdint>

#define NT    256
#define GRID  148
#define DTf   0.05f
#define MAXTILES 1024

// ---------------- Tsit5 tableau ----------------
__constant__ float c_A[6][5] = {
    {0.f, 0.f, 0.f, 0.f, 0.f},
    {0.161f, 0.f, 0.f, 0.f, 0.f},
    {-0.008480655492356989f, 0.335480655492357f, 0.f, 0.f, 0.f},
    {2.8971530571054935f, -6.359448489975075f, 4.3622954328695815f, 0.f, 0.f},
    {5.325864828439257f, -11.748883564062828f, 7.4955393428898365f, -0.09249506636175525f, 0.f},
    {5.86145544294642f, -12.92096931784711f, 8.159367898576159f, -0.071584973281401f, -0.028269050394068383f},
};
__constant__ float c_Bc[6] = {
    0.09646076681806523f, 0.01f, 0.4798896504144996f,
    1.379008574103742f, -3.290069515436081f, 2.324710524099774f
};

// k_1..k_5 stage derivatives, bf16x2 fragments, [tile][stage][q][tid] (coalesced on tid).
__device__ uint32_t g_k[(size_t)MAXTILES * 5 * 16 * NT];

// ---------------- SMEM layout (bytes) ----------------
// B-fragments PAIRED: two consecutive-ks frags of one nf stored adjacently
// (16B per lane) -> one LDS.128 feeds two mmas.
//  W1 per c (10240B): pair p(2) * nf(8) * 512B, then single ks4: nf(8) * 256B
//  W2 per c (32768B): pair p(8) * nf(8) * 512B
//  W3 per c-chunk (8192B): pair jp(2) * nf(8) * 512B
#define OW1 0          // 4 * 10240 = 40960
#define OW2 40960      // 4 * 32768 = 131072
#define OW3 172032     // 4 * 8192  = 32768
#define OB1 204800     // 256 f32
#define OB2 205824     // 256 f32
#define OB3 206848     // 64 f32
#define SMEM_BYTES 207360

// ---------------- helpers ----------------
__device__ __forceinline__ uint32_t packbf(float lo, float hi) {
    uint32_t r; asm("cvt.rn.bf16x2.f32 %0, %1, %2;" : "=r"(r) : "f"(hi), "f"(lo)); return r;
}
__device__ __forceinline__ float2 unpackbf(uint32_t v) {
    __nv_bfloat162 b = *reinterpret_cast<__nv_bfloat162*>(&v);
    return make_float2(__bfloat162float(b.x), __bfloat162float(b.y));
}
__device__ __forceinline__ float tanh_fast(float x) {
    float y; asm("tanh.approx.f32 %0, %1;" : "=f"(y) : "f"(x)); return y;
}
__device__ __forceinline__ float silu(float x) {
    float t = tanh_fast(0.5f * x);
    return fmaf(x, 0.5f * t, 0.5f * x);
}
__device__ __forceinline__ void mma_bf16(float* c, const uint32_t* a, uint32_t b0, uint32_t b1) {
    asm volatile(
        "mma.sync.aligned.m16n8k16.row.col.f32.bf16.bf16.f32 "
        "{%0,%1,%2,%3},{%4,%5,%6,%7},{%8,%9},{%0,%1,%2,%3};"
        : "+f"(c[0]), "+f"(c[1]), "+f"(c[2]), "+f"(c[3])
        : "r"(a[0]), "r"(a[1]), "r"(a[2]), "r"(a[3]), "r"(b0), "r"(b1));
}

// W[K][N] row-major f32 -> bf16 paired B-fragment SMEM (layouts above).
template<int MODE>
__device__ void conv_w(const float* __restrict__ G, int K, int N, char* dst, int tid) {
    for (int idx = tid; idx < K * N; idx += NT) {
        int k = idx / N, n = idx - k * N;
        int lane = (n & 7) * 4 + ((k & 7) >> 1);
        int kb = (((k >> 3) & 1) << 2) + ((k & 1) << 1);   // byte offset within 8B frag
        int ks = k >> 4;
        int off;
        if (MODE == 1) {
            int c = n >> 6, nf = (n >> 3) & 7;
            if (ks < 4)
                off = c * 10240 + (ks >> 1) * 4096 + nf * 512 + lane * 16 + (ks & 1) * 8 + kb;
            else
                off = c * 10240 + 8192 + nf * 256 + lane * 8 + kb;
        } else if (MODE == 2) {
            int c = n >> 6, nf = (n >> 3) & 7;
            off = c * 32768 + ((ks >> 1) * 8 + nf) * 512 + lane * 16 + (ks & 1) * 8 + kb;
        } else {
            int nf = n >> 3, c = ks >> 2, jp = (ks >> 1) & 1;
            off = c * 8192 + (jp * 8 + nf) * 512 + lane * 16 + (ks & 1) * 8 + kb;
        }
        *(__nv_bfloat16*)(dst + off) = __float2bfloat16(G[idx]);
    }
}

extern __shared__ char sm[];

__global__ void __launch_bounds__(NT, 1)
tsit5_mma_kernel(const float* __restrict__ obs, const float* __restrict__ act,
                 const float* __restrict__ gW1, const float* __restrict__ gb1,
                 const float* __restrict__ gW2, const float* __restrict__ gb2,
                 const float* __restrict__ gW3, const float* __restrict__ gb3,
                 float* __restrict__ out, int ntiles)
{
    const int tid = threadIdx.x;

    conv_w<1>(gW1,  80, 256, sm + OW1, tid);
    conv_w<2>(gW2, 256, 256, sm + OW2, tid);
    conv_w<3>(gW3, 256,  64, sm + OW3, tid);
    for (int i = tid; i < 256; i += NT) {
        ((float*)(sm + OB1))[i] = gb1[i];
        ((float*)(sm + OB2))[i] = gb2[i];
    }
    for (int i = tid; i < 64; i += NT) ((float*)(sm + OB3))[i] = gb3[i];
    __syncthreads();

    const float* B1 = (const float*)(sm + OB1);
    const float* B2 = (const float*)(sm + OB2);
    const float* B3 = (const float*)(sm + OB3);

    const int w  = tid >> 5, l = tid & 31;
    const int m0 = w * 16;
    const int rl = l >> 2;
    const int cp = (l & 3) * 2;

    for (int tile = blockIdx.x; tile < ntiles; tile += GRID) {
        const long rowlo = (long)tile * 128 + m0 + rl;
        const float* obs_lo = obs + rowlo * 64;
        const float* obs_hi = obs_lo + 8 * 64;
        uint32_t* kt = g_k + ((size_t)tile * 5) * 16 * NT + tid;

        // A-frags: ks 0..3 = x (rebuilt per stage), ks 4 = actions (persistent)
        uint32_t xa[5][4];
        {
            const float* act_lo = act + rowlo * 16;
            float2 v;
            v = *(const float2*)(act_lo + cp);           xa[4][0] = packbf(v.x, v.y);
            v = *(const float2*)(act_lo + 128 + cp);     xa[4][1] = packbf(v.x, v.y);
            v = *(const float2*)(act_lo + 8 + cp);       xa[4][2] = packbf(v.x, v.y);
            v = *(const float2*)(act_lo + 128 + 8 + cp); xa[4][3] = packbf(v.x, v.y);
        }

        #pragma unroll 1   // one body copy: no spills, small I$
        for (int st = 0; st < 6; st++) {
            // ---- build x_st A-frags: fp32 y0 (L2-hot) + dt * sum_j a[st][j]*k_j ----
            #pragma unroll
            for (int ks = 0; ks < 4; ks++)
                #pragma unroll
                for (int r = 0; r < 4; r++) {
                    const int q = ks * 4 + r;
                    const float* yp = ((r & 1) ? obs_hi : obs_lo) + ks * 16 + (r >> 1) * 8 + cp;
                    float2 v = *(const float2*)yp;
                    #pragma unroll
                    for (int j = 0; j < 5; j++)
                        if (j < st) {
                            float a = DTf * c_A[st][j];
                            float2 kk = unpackbf(kt[(j * 16 + q) * NT]);
                            v.x = fmaf(a, kk.x, v.x);
                            v.y = fmaf(a, kk.y, v.y);
                        }
                    xa[ks][r] = packbf(v.x, v.y);
                }

            // ---- GEMM1: h1 = silu(X @ W1 + b1) -> hA frags ----
            uint32_t hA[16][4];
            #pragma unroll
            for (int c = 0; c < 4; c++) {
                const uint4* q1 = (const uint4*)(sm + OW1 + c * 10240) + l;
                const uint2* s1 = (const uint2*)(sm + OW1 + c * 10240 + 8192) + l;
                float acc[8][4];
                #pragma unroll
                for (int nf = 0; nf < 8; nf++) {
                    float2 bb = *(const float2*)(B1 + c * 64 + nf * 8 + cp);
                    acc[nf][0] = bb.x; acc[nf][1] = bb.y;
                    acc[nf][2] = bb.x; acc[nf][3] = bb.y;
                }
                #pragma unroll
                for (int p = 0; p < 2; p++)
                    #pragma unroll
                    for (int nf = 0; nf < 8; nf++) {
                        uint4 bb = q1[(p * 8 + nf) * 32];
                        mma_bf16(acc[nf], xa[2 * p],     bb.x, bb.y);
                        mma_bf16(acc[nf], xa[2 * p + 1], bb.z, bb.w);
                    }
                #pragma unroll
                for (int nf = 0; nf < 8; nf++) {
                    uint2 bb = s1[nf * 32];
                    mma_bf16(acc[nf], xa[4], bb.x, bb.y);
                }
                #pragma unroll
                for (int nf = 0; nf < 8; nf++) {
                    hA[c * 4 + (nf >> 1)][(nf & 1) * 2 + 0] =
                        packbf(silu(acc[nf][0]), silu(acc[nf][1]));
                    hA[c * 4 + (nf >> 1)][(nf & 1) * 2 + 1] =
                        packbf(silu(acc[nf][2]), silu(acc[nf][3]));
                }
            }

            // ---- GEMM2 (silu) + fused GEMM3 partials (c-loop rolled) ----
            float acc3[8][4];
            #pragma unroll
            for (int nf = 0; nf < 8; nf++)
                acc3[nf][0] = acc3[nf][1] = acc3[nf][2] = acc3[nf][3] = 0.f;

            #pragma unroll 1
            for (int c = 0; c < 4; c++) {
                const uint4* q2 = (const uint4*)(sm + OW2 + c * 32768) + l;
                const uint4* q3 = (const uint4*)(sm + OW3 + c * 8192) + l;
                float acc[8][4];
                #pragma unroll
                for (int nf = 0; nf < 8; nf++) {
                    float2 bb = *(const float2*)(B2 + c * 64 + nf * 8 + cp);
                    acc[nf][0] = bb.x; acc[nf][1] = bb.y;
                    acc[nf][2] = bb.x; acc[nf][3] = bb.y;
                }
                #pragma unroll
                for (int p = 0; p < 8; p++)
                    #pragma unroll
                    for (int nf = 0; nf < 8; nf++) {
                        uint4 bb = q2[(p * 8 + nf) * 32];
                        mma_bf16(acc[nf], hA[2 * p],     bb.x, bb.y);
                        mma_bf16(acc[nf], hA[2 * p + 1], bb.z, bb.w);
                    }
                uint32_t ht[4][4];
                #pragma unroll
                for (int nf = 0; nf < 8; nf++) {
                    ht[nf >> 1][(nf & 1) * 2 + 0] =
                        packbf(silu(acc[nf][0]), silu(acc[nf][1]));
                    ht[nf >> 1][(nf & 1) * 2 + 1] =
                        packbf(silu(acc[nf][2]), silu(acc[nf][3]));
                }
                #pragma unroll
                for (int jp = 0; jp < 2; jp++)
                    #pragma unroll
                    for (int nf = 0; nf < 8; nf++) {
                        uint4 bb = q3[(jp * 8 + nf) * 32];
                        mma_bf16(acc3[nf], ht[2 * jp],     bb.x, bb.y);
                        mma_bf16(acc3[nf], ht[2 * jp + 1], bb.z, bb.w);
                    }
            }

            // ---- GEMM3 epilogue ----
            if (st < 5) {
                #pragma unroll
                for (int nf = 0; nf < 8; nf++) {
                    float2 bb = *(const float2*)(B3 + nf * 8 + cp);
                    int q = (nf >> 1) * 4 + (nf & 1) * 2;
                    kt[(st * 16 + q + 0) * NT] = packbf(acc3[nf][0] + bb.x, acc3[nf][1] + bb.y);
                    kt[(st * 16 + q + 1) * NT] = packbf(acc3[nf][2] + bb.x, acc3[nf][3] + bb.y);
                }
            } else {
                float* o_lo = out + rowlo * 64;
                float* o_hi = o_lo + 8 * 64;
                const float d5 = DTf * c_Bc[5];
                #pragma unroll
                for (int nf = 0; nf < 8; nf++) {
                    float2 bb  = *(const float2*)(B3 + nf * 8 + cp);
                    float2 ylo = *(const float2*)(obs_lo + nf * 8 + cp);
                    float2 yhi = *(const float2*)(obs_hi + nf * 8 + cp);
                    float lo0 = fmaf(d5, acc3[nf][0] + bb.x, ylo.x);
                    float lo1 = fmaf(d5, acc3[nf][1] + bb.y, ylo.y);
                    float hi0 = fmaf(d5, acc3[nf][2] + bb.x, yhi.x);
                    float hi1 = fmaf(d5, acc3[nf][3] + bb.y, yhi.y);
                    int ql = (nf >> 1) * 4 + (nf & 1) * 2, qh = ql + 1;
                    #pragma unroll
                    for (int j = 0; j < 5; j++) {
                        float d = DTf * c_Bc[j];
                        float2 klo = unpackbf(kt[(j * 16 + ql) * NT]);
                        float2 khi = unpackbf(kt[(j * 16 + qh) * NT]);
                        lo0 = fmaf(d, klo.x, lo0); lo1 = fmaf(d, klo.y, lo1);
                        hi0 = fmaf(d, khi.x, hi0); hi1 = fmaf(d, khi.y, hi1);
                    }
                    *(float2*)(o_lo + nf * 8 + cp) = make_float2(lo0, lo1);
                    *(float2*)(o_hi + nf * 8 + cp) = make_float2(hi0, hi1);
                }
            }
        }
    }
}

extern "C" void kernel_launch(void* const* d_in, const int* in_sizes, int n_in,
                              void* d_out, int out_size)
{
    const float* obs = (const float*)d_in[0];
    const float* act = (const float*)d_in[1];
    const float* W1  = (const float*)d_in[2];
    const float* b1  = (const float*)d_in[3];
    const float* W2  = (const float*)d_in[4];
    const float* b2  = (const float*)d_in[5];
    const float* W3  = (const float*)d_in[6];
    const float* b3  = (const float*)d_in[7];
    float* out = (float*)d_out;

    const int batch  = in_sizes[0] / 64;
    int ntiles = batch / 128;
    if (ntiles > MAXTILES) ntiles = MAXTILES;

    cudaFuncSetAttribute(tsit5_mma_kernel,
                         cudaFuncAttributeMaxDynamicSharedMemorySize, SMEM_BYTES);

    tsit5_mma_kernel<<<GRID, NT, SMEM_BYTES>>>(obs, act, W1, b1, W2, b2, W3, b3, out, ntiles);
}